// round 2
// baseline (speedup 1.0000x reference)
#include <cuda_runtime.h>

// ---------------------------------------------------------------------------
// FCGF point attention pipeline, fp32 SIMT baseline (round 0).
//
// Stages:
//   k_gemm1   : h_pre[N,128] = x[N,32] @ w1^T + b1            (+ BN1 partial stats)
//   k_fin1    : BN1 stats -> (alpha1, beta1) fold
//   k_gemm2   : att_pre[N,512] = relu(aff1(h_pre)) @ w2^T + b2 (+ BN2 partial stats)
//   k_fin2    : BN2 stats -> (alpha2, beta2) fold
//   k_pool    : per-segment att^T @ x partials + gp partials  (att = relu(aff2(att_pre)))
//   k_poolred : reduce pooled partials, scale by 1/L
//   k_gpred   : reduce gp partials -> out, write lengths
//   k_final   : res_bn = BN(pooled_flat @ wf^T + bf)   (BN over batch inside block)
//   k_norm    : L2 row-normalize -> out
//
// All reductions are deterministic (fixed partial slots, tree reduce). No
// atomics, no allocations, fully graph-capturable.
// ---------------------------------------------------------------------------

constexpr int C    = 32;
constexpr int K1C  = 128;
constexpr int K2C  = 512;
constexpr int FCC  = 256;
constexpr int MAXN = 524288;
constexpr int MAXB = 16;
constexpr int SCH  = 16;       // pooling row-chunks per segment
constexpr float EPS_BN = 1e-5f;

// ---- scratch (static device memory; allocations are forbidden) ----
__device__ float g_h   [(size_t)MAXN * K1C];           // 268 MB
__device__ float g_att [(size_t)MAXN * K2C];           // 1.07 GB
__device__ float g_p1s [(MAXN / 256) * K1C];
__device__ float g_p1q [(MAXN / 256) * K1C];
__device__ float g_p2s [(size_t)(MAXN / 128) * K2C];
__device__ float g_p2q [(size_t)(MAXN / 128) * K2C];
__device__ float g_a1  [K1C];
__device__ float g_bb1 [K1C];
__device__ float g_a2  [K2C];
__device__ float g_bb2 [K2C];
__device__ float g_ppool[(size_t)MAXB * SCH * K2C * C]; // 16.8 MB
__device__ float g_pgp  [(size_t)MAXB * SCH * K2C];
__device__ float g_pooled[(size_t)MAXB * K2C * C];
__device__ float g_resb [MAXB * FCC];

// ---------------------------------------------------------------------------
// GEMM1: h_pre = x @ w1^T + b1, per-channel partial (sum, sumsq).
// Block = 128 threads (one per output channel), 256 points per block.
// ---------------------------------------------------------------------------
__global__ void __launch_bounds__(128) k_gemm1(const float* __restrict__ x,
                                               const float* __restrict__ w1,
                                               const float* __restrict__ b1) {
    __shared__ float sx[256 * C];
    const int k  = threadIdx.x;
    const int p0 = blockIdx.x * 256;

    const float4* xg  = reinterpret_cast<const float4*>(x) + (size_t)p0 * (C / 4);
    float4*       sx4 = reinterpret_cast<float4*>(sx);
#pragma unroll
    for (int i = 0; i < (256 * C / 4) / 128; i++)
        sx4[threadIdx.x + i * 128] = xg[threadIdx.x + i * 128];

    float w[C];
#pragma unroll
    for (int c = 0; c < C; c++) w[c] = __ldg(&w1[k * C + c]);
    const float bias = __ldg(&b1[k]);
    __syncthreads();

    float s = 0.f, q = 0.f;
    float* hp = g_h + (size_t)p0 * K1C + k;
    for (int p = 0; p < 256; p++) {
        const float4* xr = reinterpret_cast<const float4*>(sx + p * C);
        float acc = bias;
#pragma unroll
        for (int c4 = 0; c4 < C / 4; c4++) {
            float4 v = xr[c4];
            acc = fmaf(w[c4 * 4 + 0], v.x, acc);
            acc = fmaf(w[c4 * 4 + 1], v.y, acc);
            acc = fmaf(w[c4 * 4 + 2], v.z, acc);
            acc = fmaf(w[c4 * 4 + 3], v.w, acc);
        }
        hp[(size_t)p * K1C] = acc;
        s += acc;
        q = fmaf(acc, acc, q);
    }
    g_p1s[blockIdx.x * K1C + k] = s;
    g_p1q[blockIdx.x * K1C + k] = q;
}

// ---------------------------------------------------------------------------
// BN finalize kernels: reduce partials, emit folded affine (alpha, beta).
// ---------------------------------------------------------------------------
__global__ void k_fin1(const float* __restrict__ g, const float* __restrict__ be,
                       int nblk, float invN) {
    const int ch = blockIdx.x;
    __shared__ float rs[256], rq[256];
    float s = 0.f, q = 0.f;
    for (int i = threadIdx.x; i < nblk; i += 256) {
        s += g_p1s[i * K1C + ch];
        q += g_p1q[i * K1C + ch];
    }
    rs[threadIdx.x] = s; rq[threadIdx.x] = q;
    __syncthreads();
    for (int o = 128; o > 0; o >>= 1) {
        if (threadIdx.x < o) {
            rs[threadIdx.x] += rs[threadIdx.x + o];
            rq[threadIdx.x] += rq[threadIdx.x + o];
        }
        __syncthreads();
    }
    if (threadIdx.x == 0) {
        float mu   = rs[0] * invN;
        float var  = rq[0] * invN - mu * mu;
        float rstd = rsqrtf(var + EPS_BN);
        float a    = g[ch] * rstd;
        g_a1[ch]  = a;
        g_bb1[ch] = be[ch] - mu * a;
    }
}

__global__ void k_fin2(const float* __restrict__ g, const float* __restrict__ be,
                       int nblk, float invN) {
    const int ch = blockIdx.x;
    __shared__ float rs[256], rq[256];
    float s = 0.f, q = 0.f;
    for (int i = threadIdx.x; i < nblk; i += 256) {
        s += g_p2s[(size_t)i * K2C + ch];
        q += g_p2q[(size_t)i * K2C + ch];
    }
    rs[threadIdx.x] = s; rq[threadIdx.x] = q;
    __syncthreads();
    for (int o = 128; o > 0; o >>= 1) {
        if (threadIdx.x < o) {
            rs[threadIdx.x] += rs[threadIdx.x + o];
            rq[threadIdx.x] += rq[threadIdx.x + o];
        }
        __syncthreads();
    }
    if (threadIdx.x == 0) {
        float mu   = rs[0] * invN;
        float var  = rq[0] * invN - mu * mu;
        float rstd = rsqrtf(var + EPS_BN);
        float a    = g[ch] * rstd;
        g_a2[ch]  = a;
        g_bb2[ch] = be[ch] - mu * a;
    }
}

// ---------------------------------------------------------------------------
// GEMM2: att_pre = relu(alpha1*h_pre + beta1) @ w2^T + b2, + BN2 partials.
// 128x128 tile, 256 threads, 8x8 per thread, K-chunk 16.
// grid = (K2C/128, N/128): colblk fastest so L2 reuses the A tile.
// ---------------------------------------------------------------------------
constexpr int TST = 132;   // padded smem row stride

__global__ void __launch_bounds__(256) k_gemm2(const float* __restrict__ w2,
                                               const float* __restrict__ b2) {
    __shared__ float As[16 * TST];
    __shared__ float Bs[16 * TST];
    __shared__ float sA1[K1C], sB1[K1C];

    const int tid = threadIdx.x;
    const int tx = tid & 15, ty = tid >> 4;
    const int m0 = ty * 8, n0 = tx * 8;
    const int col0 = blockIdx.x * 128;
    const int row0 = blockIdx.y * 128;

    if (tid < K1C) { sA1[tid] = g_a1[tid]; sB1[tid] = g_bb1[tid]; }

    float acc[8][8];
#pragma unroll
    for (int i = 0; i < 8; i++)
#pragma unroll
        for (int j = 0; j < 8; j++) acc[i][j] = 0.f;

    __syncthreads();  // sA1/sB1 visible

    for (int kt = 0; kt < K1C; kt += 16) {
#pragma unroll
        for (int l = 0; l < 2; l++) {
            int qi = tid + l * 256;     // 0..511
            int m  = qi >> 2;           // 0..127
            int kq = (qi & 3) * 4;      // 0,4,8,12
            int kg = kt + kq;

            float4 v = *reinterpret_cast<const float4*>(
                &g_h[(size_t)(row0 + m) * K1C + kg]);
            v.x = fmaxf(fmaf(sA1[kg + 0], v.x, sB1[kg + 0]), 0.f);
            v.y = fmaxf(fmaf(sA1[kg + 1], v.y, sB1[kg + 1]), 0.f);
            v.z = fmaxf(fmaf(sA1[kg + 2], v.z, sB1[kg + 2]), 0.f);
            v.w = fmaxf(fmaf(sA1[kg + 3], v.w, sB1[kg + 3]), 0.f);
            As[(kq + 0) * TST + m] = v.x;
            As[(kq + 1) * TST + m] = v.y;
            As[(kq + 2) * TST + m] = v.z;
            As[(kq + 3) * TST + m] = v.w;

            float4 wv = *reinterpret_cast<const float4*>(
                &w2[(size_t)(col0 + m) * K1C + kg]);
            Bs[(kq + 0) * TST + m] = wv.x;
            Bs[(kq + 1) * TST + m] = wv.y;
            Bs[(kq + 2) * TST + m] = wv.z;
            Bs[(kq + 3) * TST + m] = wv.w;
        }
        __syncthreads();

#pragma unroll
        for (int kk = 0; kk < 16; kk++) {
            float a[8], b[8];
#pragma unroll
            for (int i = 0; i < 8; i++) a[i] = As[kk * TST + m0 + i];
#pragma unroll
            for (int j = 0; j < 8; j++) b[j] = Bs[kk * TST + n0 + j];
#pragma unroll
            for (int i = 0; i < 8; i++)
#pragma unroll
                for (int j = 0; j < 8; j++)
                    acc[i][j] = fmaf(a[i], b[j], acc[i][j]);
        }
        __syncthreads();
    }

    // epilogue: add bias, store, per-column partial stats
    float bias[8];
#pragma unroll
    for (int j = 0; j < 8; j++) bias[j] = __ldg(&b2[col0 + n0 + j]);

    float cs[8], cq[8];
#pragma unroll
    for (int j = 0; j < 8; j++) { cs[j] = 0.f; cq[j] = 0.f; }

#pragma unroll
    for (int i = 0; i < 8; i++) {
        float v[8];
#pragma unroll
        for (int j = 0; j < 8; j++) {
            v[j] = acc[i][j] + bias[j];
            cs[j] += v[j];
            cq[j] = fmaf(v[j], v[j], cq[j]);
        }
        float* dst = &g_att[(size_t)(row0 + m0 + i) * K2C + col0 + n0];
        *reinterpret_cast<float4*>(dst)     = make_float4(v[0], v[1], v[2], v[3]);
        *reinterpret_cast<float4*>(dst + 4) = make_float4(v[4], v[5], v[6], v[7]);
    }

    // block-level column reduction via smem (reuse As)
    float* red = As;
#pragma unroll
    for (int j = 0; j < 8; j++) red[ty * 128 + n0 + j] = cs[j];
    __syncthreads();
    float stot = 0.f;
    if (tid < 128) {
#pragma unroll
        for (int t = 0; t < 16; t++) stot += red[t * 128 + tid];
    }
    __syncthreads();
#pragma unroll
    for (int j = 0; j < 8; j++) red[ty * 128 + n0 + j] = cq[j];
    __syncthreads();
    if (tid < 128) {
        float qtot = 0.f;
#pragma unroll
        for (int t = 0; t < 16; t++) qtot += red[t * 128 + tid];
        g_p2s[(size_t)blockIdx.y * K2C + col0 + tid] = stot;
        g_p2q[(size_t)blockIdx.y * K2C + col0 + tid] = qtot;
    }
}

// ---------------------------------------------------------------------------
// Pooling: per (segment, row-chunk, 64-channel group):
//   ppool[k,c] += relu(aff2(att_pre[n,k])) * x[n,c];  pgp[k] += att
// grid = (8 kgroups, B*SCH chunks), 256 threads: thread = (k in 64, cgroup of 8).
// ---------------------------------------------------------------------------
__global__ void __launch_bounds__(256) k_pool(const float* __restrict__ x,
                                              int L, int rowsPerChunk) {
    __shared__ float satt[32 * 64];
    __shared__ float sx[32 * C];
    __shared__ float sA2[64], sB2[64];

    const int tid = threadIdx.x;
    const int k0  = blockIdx.x * 64;
    const int b   = blockIdx.y / SCH;
    const int s   = blockIdx.y % SCH;

    if (tid < 64) { sA2[tid] = g_a2[k0 + tid]; sB2[tid] = g_bb2[k0 + tid]; }

    const int kl = tid & 63, cg = tid >> 6;
    const int rowBase = b * L + s * rowsPerChunk;

    float acc[8];
#pragma unroll
    for (int j = 0; j < 8; j++) acc[j] = 0.f;
    float gps = 0.f;
    __syncthreads();

    for (int r0 = 0; r0 < rowsPerChunk; r0 += 32) {
#pragma unroll
        for (int l = 0; l < 3; l++) {
            int qi  = tid + l * 256;   // 0..767
            int r   = qi / 24;
            int pos = qi % 24;
            int grow = rowBase + r0 + r;
            if (pos < 16) {
                int kk = pos * 4;
                float4 v = *reinterpret_cast<const float4*>(
                    &g_att[(size_t)grow * K2C + k0 + kk]);
                v.x = fmaxf(fmaf(sA2[kk + 0], v.x, sB2[kk + 0]), 0.f);
                v.y = fmaxf(fmaf(sA2[kk + 1], v.y, sB2[kk + 1]), 0.f);
                v.z = fmaxf(fmaf(sA2[kk + 2], v.z, sB2[kk + 2]), 0.f);
                v.w = fmaxf(fmaf(sA2[kk + 3], v.w, sB2[kk + 3]), 0.f);
                *reinterpret_cast<float4*>(&satt[r * 64 + kk]) = v;
            } else {
                int xq = (pos - 16) * 4;
                *reinterpret_cast<float4*>(&sx[r * C + xq]) =
                    *reinterpret_cast<const float4*>(&x[(size_t)grow * C + xq]);
            }
        }
        __syncthreads();

        const float4* sxv = reinterpret_cast<const float4*>(sx);
#pragma unroll 4
        for (int r = 0; r < 32; r++) {
            float a = satt[r * 64 + kl];
            gps += a;
            float4 u0 = sxv[r * 8 + cg * 2];
            float4 u1 = sxv[r * 8 + cg * 2 + 1];
            acc[0] = fmaf(a, u0.x, acc[0]);
            acc[1] = fmaf(a, u0.y, acc[1]);
            acc[2] = fmaf(a, u0.z, acc[2]);
            acc[3] = fmaf(a, u0.w, acc[3]);
            acc[4] = fmaf(a, u1.x, acc[4]);
            acc[5] = fmaf(a, u1.y, acc[5]);
            acc[6] = fmaf(a, u1.z, acc[6]);
            acc[7] = fmaf(a, u1.w, acc[7]);
        }
        __syncthreads();
    }

    size_t base = ((size_t)(b * SCH + s) * K2C + k0 + kl) * C + cg * 8;
    *reinterpret_cast<float4*>(&g_ppool[base])     = make_float4(acc[0], acc[1], acc[2], acc[3]);
    *reinterpret_cast<float4*>(&g_ppool[base + 4]) = make_float4(acc[4], acc[5], acc[6], acc[7]);
    if (cg == 0)
        g_pgp[(size_t)(b * SCH + s) * K2C + k0 + kl] = gps;
}

__global__ void k_poolred(float invL, int B) {
    int idx = blockIdx.x * 256 + threadIdx.x;
    int tot = B * K2C * C;
    if (idx >= tot) return;
    int b = idx / (K2C * C), rem = idx % (K2C * C);
    float s = 0.f;
#pragma unroll
    for (int t = 0; t < SCH; t++)
        s += g_ppool[(size_t)(b * SCH + t) * (K2C * C) + rem];
    g_pooled[idx] = s * invL;
}

__global__ void k_gpred(float* __restrict__ out, int B, int L) {
    int idx = blockIdx.x * 256 + threadIdx.x;
    if (idx >= B * K2C) return;
    int b = idx / K2C, k = idx % K2C;
    float s = 0.f;
#pragma unroll
    for (int t = 0; t < SCH; t++)
        s += g_pgp[(size_t)(b * SCH + t) * K2C + k];
    out[(size_t)B * FCC + (size_t)b * K2C + k] = s;
    if (k == 0)
        out[(size_t)B * (FCC + K2C) + b] = (float)L;
}

// ---------------------------------------------------------------------------
// Final FC + BN over batch: one block per output channel f; block holds all B
// dot products so BN stats are computed exactly in-block.
// ---------------------------------------------------------------------------
__global__ void __launch_bounds__(128) k_final(const float* __restrict__ wf,
                                               const float* __restrict__ bf,
                                               const float* __restrict__ gf,
                                               const float* __restrict__ bef,
                                               int B) {
    const int f = blockIdx.x;
    const int tid = threadIdx.x;
    const int nq = (K2C * C) / 4;   // 4096 float4s per row

    float acc[MAXB];
#pragma unroll
    for (int b = 0; b < MAXB; b++) acc[b] = 0.f;

    const float4* wf4 = reinterpret_cast<const float4*>(wf) + (size_t)f * nq;
    const float4* p4  = reinterpret_cast<const float4*>(g_pooled);
    for (int i = tid; i < nq; i += 128) {
        float4 wv = wf4[i];
        for (int b = 0; b < B; b++) {
            float4 pv = p4[(size_t)b * nq + i];
            float d = wv.x * pv.x + wv.y * pv.y + wv.z * pv.z + wv.w * pv.w;
            acc[b] += d;
        }
    }

    __shared__ float red[MAXB * 128];
    for (int b = 0; b < B; b++) red[b * 128 + tid] = acc[b];
    __syncthreads();
    for (int o = 64; o > 0; o >>= 1) {
        if (tid < o)
            for (int b = 0; b < B; b++)
                red[b * 128 + tid] += red[b * 128 + tid + o];
        __syncthreads();
    }

    __shared__ float sv[MAXB];
    __shared__ float smu, srstd;
    if (tid < B) sv[tid] = red[tid * 128] + bf[f];
    __syncthreads();
    if (tid == 0) {
        float mu = 0.f;
        for (int b = 0; b < B; b++) mu += sv[b];
        mu /= (float)B;
        float var = 0.f;
        for (int b = 0; b < B; b++) { float d = sv[b] - mu; var += d * d; }
        var /= (float)B;
        smu = mu;
        srstd = rsqrtf(var + EPS_BN);
    }
    __syncthreads();
    if (tid < B)
        g_resb[tid * FCC + f] = (sv[tid] - smu) * srstd * gf[f] + bef[f];
}

__global__ void __launch_bounds__(FCC) k_norm(float* __restrict__ out) {
    const int b = blockIdx.x;
    const int f = threadIdx.x;
    float v = g_resb[b * FCC + f];
    __shared__ float red[FCC];
    red[f] = v * v;
    __syncthreads();
    for (int o = FCC / 2; o > 0; o >>= 1) {
        if (f < o) red[f] += red[f + o];
        __syncthreads();
    }
    __shared__ float sinv;
    if (f == 0) sinv = 1.f / fmaxf(sqrtf(red[0]), 1e-12f);
    __syncthreads();
    out[(size_t)b * FCC + f] = v * sinv;
}

// ---------------------------------------------------------------------------
extern "C" void kernel_launch(void* const* d_in, const int* in_sizes, int n_in,
                              void* d_out, int out_size) {
    const float* x   = (const float*)d_in[0];
    const float* w1  = (const float*)d_in[1];
    const float* b1  = (const float*)d_in[2];
    const float* g1  = (const float*)d_in[3];
    const float* be1 = (const float*)d_in[4];
    const float* w2  = (const float*)d_in[5];
    const float* b2  = (const float*)d_in[6];
    const float* g2  = (const float*)d_in[7];
    const float* be2 = (const float*)d_in[8];
    const float* wf  = (const float*)d_in[9];
    const float* bf  = (const float*)d_in[10];
    const float* gf  = (const float*)d_in[11];
    const float* bef = (const float*)d_in[12];
    float* out = (float*)d_out;

    const int N = in_sizes[0] / C;                  // 524288
    const int B = out_size / (FCC + K2C + 1);       // 16
    const int L = N / B;                            // 32768
    const int rowsPerChunk = L / SCH;               // 2048

    k_gemm1<<<N / 256, 128>>>(x, w1, b1);
    k_fin1<<<K1C, 256>>>(g1, be1, N / 256, 1.f / (float)N);
    k_gemm2<<<dim3(K2C / 128, N / 128), 256>>>(w2, b2);
    k_fin2<<<K2C, 256>>>(g2, be2, N / 128, 1.f / (float)N);
    k_pool<<<dim3(K2C / 64, B * SCH), 256>>>(x, L, rowsPerChunk);
    k_poolred<<<(B * K2C * C + 255) / 256, 256>>>(1.f / (float)L, B);
    k_gpred<<<(B * K2C + 255) / 256, 256>>>(out, B, L);
    k_final<<<FCC, 128>>>(wf, bf, gf, bef, B);
    k_norm<<<B, FCC>>>(out);
}

// round 4
// speedup vs baseline: 1.9891x; 1.9891x over previous
#include <cuda_runtime.h>
#include <cstdint>

constexpr int C = 32, K1C = 128, K2C = 512, FCC = 256;
constexpr int MAXN = 524288, MAXB = 16, SCH = 16;
constexpr float EPS_BN = 1e-5f;

__device__ float g_h   [(size_t)MAXN * K1C];
__device__ float g_att [(size_t)K2C * MAXN];          // attT [512][N]
__device__ float g_p1s [(MAXN / 256) * K1C];
__device__ float g_p1q [(MAXN / 256) * K1C];
__device__ float g_p2s [(size_t)K2C * (MAXN / 128)];  // [ch][blk]
__device__ float g_p2q [(size_t)K2C * (MAXN / 128)];
__device__ float g_a1[K1C], g_bb1[K1C], g_a2[K2C], g_bb2[K2C];
__device__ float g_ppool[(size_t)MAXB * SCH * K2C * C];
__device__ float g_pgp  [(size_t)MAXB * SCH * K2C];
__device__ float g_pooled[(size_t)MAXB * K2C * C];
__device__ float g_resb [MAXB * FCC];

__device__ __forceinline__ float tf32r(float v) {
    float o; asm("cvt.rna.tf32.f32 %0, %1;" : "=f"(o) : "f"(v)); return o;
}
// D += A*B, m16n8k8 tf32 (HMMA, sm_80+ path — valid on plain sm_103 target)
__device__ __forceinline__ void mma8(float* d, const uint32_t* a, const uint32_t* b) {
    asm volatile(
        "mma.sync.aligned.m16n8k8.row.col.f32.tf32.tf32.f32 "
        "{%0,%1,%2,%3}, {%4,%5,%6,%7}, {%8,%9}, {%0,%1,%2,%3};"
        : "+f"(d[0]), "+f"(d[1]), "+f"(d[2]), "+f"(d[3])
        : "r"(a[0]), "r"(a[1]), "r"(a[2]), "r"(a[3]), "r"(b[0]), "r"(b[1]));
}

// ---------------- GEMM1 (fp32 SIMT; ~4% of runtime) ----------------
__global__ void __launch_bounds__(128) k_gemm1(const float* __restrict__ x,
                                               const float* __restrict__ w1,
                                               const float* __restrict__ b1) {
    __shared__ float sx[256 * C];
    const int k = threadIdx.x, p0 = blockIdx.x * 256;
    const float4* xg = reinterpret_cast<const float4*>(x) + (size_t)p0 * (C / 4);
    float4* sx4 = reinterpret_cast<float4*>(sx);
#pragma unroll
    for (int i = 0; i < 16; i++) sx4[threadIdx.x + i * 128] = xg[threadIdx.x + i * 128];
    float w[C];
#pragma unroll
    for (int c = 0; c < C; c++) w[c] = __ldg(&w1[k * C + c]);
    const float bias = __ldg(&b1[k]);
    __syncthreads();
    float s = 0.f, q = 0.f;
    float* hp = g_h + (size_t)p0 * K1C + k;
    for (int p = 0; p < 256; p++) {
        const float4* xr = reinterpret_cast<const float4*>(sx + p * C);
        float acc = bias;
#pragma unroll
        for (int c4 = 0; c4 < 8; c4++) {
            float4 v = xr[c4];
            acc = fmaf(w[c4 * 4 + 0], v.x, acc);
            acc = fmaf(w[c4 * 4 + 1], v.y, acc);
            acc = fmaf(w[c4 * 4 + 2], v.z, acc);
            acc = fmaf(w[c4 * 4 + 3], v.w, acc);
        }
        hp[(size_t)p * K1C] = acc;
        s += acc; q = fmaf(acc, acc, q);
    }
    g_p1s[blockIdx.x * K1C + k] = s;
    g_p1q[blockIdx.x * K1C + k] = q;
}

// ---------------- BN finalize ----------------
__global__ void k_fin1(const float* __restrict__ g, const float* __restrict__ be,
                       int nblk, float invN) {
    const int ch = blockIdx.x;
    __shared__ float rs[256], rq[256];
    float s = 0.f, q = 0.f;
    for (int i = threadIdx.x; i < nblk; i += 256) {
        s += g_p1s[i * K1C + ch]; q += g_p1q[i * K1C + ch];
    }
    rs[threadIdx.x] = s; rq[threadIdx.x] = q; __syncthreads();
    for (int o = 128; o > 0; o >>= 1) {
        if (threadIdx.x < o) { rs[threadIdx.x] += rs[threadIdx.x + o]; rq[threadIdx.x] += rq[threadIdx.x + o]; }
        __syncthreads();
    }
    if (threadIdx.x == 0) {
        float mu = rs[0] * invN, var = rq[0] * invN - mu * mu;
        float a = g[ch] * rsqrtf(var + EPS_BN);
        g_a1[ch] = a; g_bb1[ch] = be[ch] - mu * a;
    }
}
__global__ void k_fin2(const float* __restrict__ g, const float* __restrict__ be,
                       int nblk, float invN) {
    const int ch = blockIdx.x;
    __shared__ float rs[256], rq[256];
    float s = 0.f, q = 0.f;
    const float* ps = g_p2s + (size_t)ch * nblk;
    const float* pq = g_p2q + (size_t)ch * nblk;
    for (int i = threadIdx.x; i < nblk; i += 256) { s += ps[i]; q += pq[i]; }
    rs[threadIdx.x] = s; rq[threadIdx.x] = q; __syncthreads();
    for (int o = 128; o > 0; o >>= 1) {
        if (threadIdx.x < o) { rs[threadIdx.x] += rs[threadIdx.x + o]; rq[threadIdx.x] += rq[threadIdx.x + o]; }
        __syncthreads();
    }
    if (threadIdx.x == 0) {
        float mu = rs[0] * invN, var = rq[0] * invN - mu * mu;
        float a = g[ch] * rsqrtf(var + EPS_BN);
        g_a2[ch] = a; g_bb2[ch] = be[ch] - mu * a;
    }
}

// ---------------- GEMM2: tf32 mma.sync ----------------
// Block: 256 thr (8 warps, 4x2: warp tile m32 x n64), tile M=128 pts x N=512 ch
// (4 passes of 128), K=128. A = relu(aff1(g_h)) staged in fragment order.
// smem floats: As 16384 | Bs 16384 | sA1 128 | sB1 128 | sb2 512 | ps 512 | pq 512
constexpr int G2_SMEM_FLOATS = 16384 + 16384 + 128 + 128 + 512 + 512 + 512;

__global__ void __launch_bounds__(256, 1) k_gemm2(const float* __restrict__ w2,
                                                  const float* __restrict__ b2,
                                                  int Np, int nblk) {
    extern __shared__ float sm[];
    float* As = sm;
    float* Bs = sm + 16384;
    float* sA1 = sm + 32768;
    float* sB1 = sA1 + 128;
    float* sb2 = sB1 + 128;
    float* ps  = sb2 + 512;
    float* pq  = ps + 512;
    const int tid = threadIdx.x, lane = tid & 31, warp = tid >> 5;
    const int wm = warp >> 1, wn = warp & 1;
    const int gid = lane >> 2, tig = lane & 3;
    const int row0 = blockIdx.x * 128;

    if (tid < 128) { sA1[tid] = g_a1[tid]; sB1[tid] = g_bb1[tid]; }
    sb2[tid] = __ldg(&b2[tid]); sb2[tid + 256] = __ldg(&b2[tid + 256]);
    __syncthreads();

    // stage A (fragment order, xor-swizzled): one row per warp per iter
#pragma unroll
    for (int i = 0; i < 16; i++) {
        int q = tid + i * 256;
        int r = q >> 5, k4 = (q & 31) * 4;
        float4 v = *reinterpret_cast<const float4*>(&g_h[(size_t)(row0 + r) * K1C + k4]);
        float vv[4];
        vv[0] = tf32r(fmaxf(fmaf(sA1[k4 + 0], v.x, sB1[k4 + 0]), 0.f));
        vv[1] = tf32r(fmaxf(fmaf(sA1[k4 + 1], v.y, sB1[k4 + 1]), 0.f));
        vv[2] = tf32r(fmaxf(fmaf(sA1[k4 + 2], v.z, sB1[k4 + 2]), 0.f));
        vv[3] = tf32r(fmaxf(fmaf(sA1[k4 + 3], v.w, sB1[k4 + 3]), 0.f));
        int mt = r >> 4, rr = r & 15;
        int kt = k4 >> 3, reg = (rr >> 3) + ((k4 & 7) >> 2) * 2;
        int slotb = (rr & 7) * 4;
        float* base = As + (mt * 16 + kt) * 128;
#pragma unroll
        for (int j = 0; j < 4; j++)
            base[((slotb + j) ^ (kt & 7)) * 4 + reg] = vv[j];
    }

    for (int pass = 0; pass < 4; pass++) {
        // stage B = w2 rows [pass*128, +128)
#pragma unroll
        for (int i = 0; i < 16; i++) {
            int q = tid + i * 256;
            int r = q >> 5, k4 = (q & 31) * 4;
            float4 v = *reinterpret_cast<const float4*>(&w2[(size_t)(pass * 128 + r) * K1C + k4]);
            float vv[4] = { tf32r(v.x), tf32r(v.y), tf32r(v.z), tf32r(v.w) };
            int nt = r >> 3, rr = r & 7;
            int kt = k4 >> 3, reg = (k4 & 7) >> 2;
            int slotb = rr * 4;
            float* base = Bs + (nt * 16 + kt) * 64;
#pragma unroll
            for (int j = 0; j < 4; j++)
                base[((slotb + j) ^ (kt & 7)) * 2 + reg] = vv[j];
        }
        __syncthreads();

        float d[2][8][4] = {};
#pragma unroll
        for (int kt = 0; kt < 16; kt++) {
            int lp = lane ^ (kt & 7);
            uint32_t a[2][4], b[8][2];
#pragma unroll
            for (int mi = 0; mi < 2; mi++) {
                int mt = wm * 2 + mi;
                *reinterpret_cast<float4*>(a[mi]) =
                    *reinterpret_cast<const float4*>(&As[(mt * 16 + kt) * 128 + lp * 4]);
            }
#pragma unroll
            for (int ni = 0; ni < 8; ni++) {
                int nt = wn * 8 + ni;
                *reinterpret_cast<float2*>(b[ni]) =
                    *reinterpret_cast<const float2*>(&Bs[(nt * 16 + kt) * 64 + lp * 2]);
            }
#pragma unroll
            for (int mi = 0; mi < 2; mi++)
#pragma unroll
                for (int ni = 0; ni < 8; ni++)
                    mma8(d[mi][ni], a[mi], b[ni]);
        }

        // epilogue: bias, store attT, BN2 partials
#pragma unroll
        for (int ni = 0; ni < 8; ni++) {
#pragma unroll
            for (int par = 0; par < 2; par++) {
                int chp = wn * 64 + ni * 8 + tig * 2 + par;
                int ch = pass * 128 + chp;
                float bias = sb2[ch];
                float s = 0.f, qq = 0.f;
#pragma unroll
                for (int mi = 0; mi < 2; mi++) {
                    float v0 = d[mi][ni][par] + bias;
                    float v1 = d[mi][ni][par + 2] + bias;
                    int ptb = row0 + wm * 32 + mi * 16 + gid;
                    g_att[(size_t)ch * Np + ptb] = v0;
                    g_att[(size_t)ch * Np + ptb + 8] = v1;
                    s += v0 + v1;
                    qq = fmaf(v0, v0, qq); qq = fmaf(v1, v1, qq);
                }
#pragma unroll
                for (int o = 4; o < 32; o <<= 1) {
                    s  += __shfl_xor_sync(0xFFFFFFFFu, s, o);
                    qq += __shfl_xor_sync(0xFFFFFFFFu, qq, o);
                }
                if (gid == 0) { ps[wm * 128 + chp] = s; pq[wm * 128 + chp] = qq; }
            }
        }
        __syncthreads();
        if (tid < 128) {
            float s = ps[tid] + ps[128 + tid] + ps[256 + tid] + ps[384 + tid];
            float qq = pq[tid] + pq[128 + tid] + pq[256 + tid] + pq[384 + tid];
            g_p2s[(size_t)(pass * 128 + tid) * nblk + blockIdx.x] = s;
            g_p2q[(size_t)(pass * 128 + tid) * nblk + blockIdx.x] = qq;
        }
        __syncthreads();
    }
}

// ---------------- Pool: tf32 mma.sync, D[128ch x 40], col 32 = ones -> gp ----
__global__ void __launch_bounds__(256) k_pool(const float* __restrict__ x,
                                              int Np, int L, int rpc) {
    __shared__ float Af[8192];   // [8 mt][8 kt][32][4]
    __shared__ float Bf[2560];   // [5 nt][8 kt][32][2]
    __shared__ float sA2[128], sB2c[128];
    const int tid = threadIdx.x, lane = tid & 31, warp = tid >> 5;
    const int gid = lane >> 2, tig = lane & 3;
    const int ch0 = blockIdx.x * 128;
    const int b = blockIdx.y / SCH, s = blockIdx.y % SCH;
    const int pt0g = b * L + s * rpc;

    if (tid < 128) { sA2[tid] = g_a2[ch0 + tid]; sB2c[tid] = g_bb2[ch0 + tid]; }
    // stage constant nt=4 tile: col 32 = 1.0 (gp), cols 33..39 = 0
    for (int idx = tid; idx < 512; idx += 256) {
        int laneq = (idx >> 1) & 31;
        Bf[2048 + idx] = ((laneq >> 2) == 0) ? 1.f : 0.f;
    }
    __syncthreads();

    float d[5][4] = {};
    for (int ck = 0; ck < rpc; ck += 64) {
        // stage A: relu(aff2(attT[128ch][64pt])) in frag order
#pragma unroll
        for (int i = 0; i < 8; i++) {
            int q = tid + i * 256;
            int r = q >> 4, p4 = (q & 15) * 4;
            float4 v = *reinterpret_cast<const float4*>(
                &g_att[(size_t)(ch0 + r) * Np + pt0g + ck + p4]);
            float a = sA2[r], bb = sB2c[r];
            float vv[4];
            vv[0] = tf32r(fmaxf(fmaf(a, v.x, bb), 0.f));
            vv[1] = tf32r(fmaxf(fmaf(a, v.y, bb), 0.f));
            vv[2] = tf32r(fmaxf(fmaf(a, v.z, bb), 0.f));
            vv[3] = tf32r(fmaxf(fmaf(a, v.w, bb), 0.f));
            int mt = r >> 4, rr = r & 15;
            int kt = p4 >> 3, reg = (rr >> 3) + ((p4 & 7) >> 2) * 2;
            int slotb = (rr & 7) * 4;
            float* base = Af + (mt * 8 + kt) * 128;
#pragma unroll
            for (int j = 0; j < 4; j++)
                base[((slotb + j) ^ (kt & 7)) * 4 + reg] = vv[j];
        }
        // stage B: x[64pt][32c] in frag order (k=pt, n=c)
#pragma unroll
        for (int i = 0; i < 2; i++) {
            int q = tid + i * 256;
            int p = q >> 3, c4 = (q & 7) * 4;
            float4 v = *reinterpret_cast<const float4*>(
                &x[(size_t)(pt0g + ck + p) * C + c4]);
            float vv[4] = { tf32r(v.x), tf32r(v.y), tf32r(v.z), tf32r(v.w) };
            int kt = p >> 3, kb = p & 7, reg = kb >> 2;
            int nt = c4 >> 3, sb = c4 & 7;
            float* base = Bf + (nt * 8 + kt) * 64;
#pragma unroll
            for (int j = 0; j < 4; j++) {
                int slot = (sb + j) * 4 + (kb & 3);
                base[(slot ^ ((nt & 3) << 3)) * 2 + reg] = vv[j];
            }
        }
        __syncthreads();
#pragma unroll
        for (int kt = 0; kt < 8; kt++) {
            int lpA = lane ^ (kt & 7);
            uint32_t a[4];
            *reinterpret_cast<float4*>(a) =
                *reinterpret_cast<const float4*>(&Af[(warp * 8 + kt) * 128 + lpA * 4]);
#pragma unroll
            for (int ni = 0; ni < 5; ni++) {
                int lpB = lane ^ ((ni & 3) << 3);
                uint32_t bb[2];
                *reinterpret_cast<float2*>(bb) =
                    *reinterpret_cast<const float2*>(&Bf[(ni * 8 + kt) * 64 + lpB * 2]);
                mma8(d[ni], a, bb);
            }
        }
        __syncthreads();
    }

    const int seg = b * SCH + s;
#pragma unroll
    for (int ni = 0; ni < 5; ni++) {
#pragma unroll
        for (int c = 0; c < 4; c++) {
            int n = ni * 8 + tig * 2 + (c & 1);
            int ch = ch0 + warp * 16 + gid + 8 * (c >> 1);
            if (n < 32)
                g_ppool[((size_t)seg * K2C + ch) * C + n] = d[ni][c];
            else if (n == 32)
                g_pgp[(size_t)seg * K2C + ch] = d[ni][c];
        }
    }
}

__global__ void k_poolred(float invL, int B) {
    int idx = blockIdx.x * 256 + threadIdx.x;
    if (idx >= B * K2C * C) return;
    int b = idx / (K2C * C), rem = idx % (K2C * C);
    float s = 0.f;
#pragma unroll
    for (int t = 0; t < SCH; t++) s += g_ppool[(size_t)(b * SCH + t) * (K2C * C) + rem];
    g_pooled[idx] = s * invL;
}
__global__ void k_gpred(float* __restrict__ out, int B, int L) {
    int idx = blockIdx.x * 256 + threadIdx.x;
    if (idx >= B * K2C) return;
    int b = idx / K2C, k = idx % K2C;
    float s = 0.f;
#pragma unroll
    for (int t = 0; t < SCH; t++) s += g_pgp[(size_t)(b * SCH + t) * K2C + k];
    out[(size_t)B * FCC + (size_t)b * K2C + k] = s;
    if (k == 0) out[(size_t)B * (FCC + K2C) + b] = (float)L;
}

// ---------------- final FC + BN + L2 norm ----------------
__global__ void __launch_bounds__(128) k_final(const float* __restrict__ wf,
                                               const float* __restrict__ bf,
                                               const float* __restrict__ gf,
                                               const float* __restrict__ bef, int B) {
    const int f = blockIdx.x, tid = threadIdx.x, nq = (K2C * C) / 4;
    float acc[MAXB];
#pragma unroll
    for (int b = 0; b < MAXB; b++) acc[b] = 0.f;
    const float4* wf4 = reinterpret_cast<const float4*>(wf) + (size_t)f * nq;
    const float4* p4 = reinterpret_cast<const float4*>(g_pooled);
    for (int i = tid; i < nq; i += 128) {
        float4 wv = wf4[i];
        for (int b = 0; b < B; b++) {
            float4 pv = p4[(size_t)b * nq + i];
            acc[b] += wv.x * pv.x + wv.y * pv.y + wv.z * pv.z + wv.w * pv.w;
        }
    }
    __shared__ float red[MAXB * 128];
    for (int b = 0; b < B; b++) red[b * 128 + tid] = acc[b];
    __syncthreads();
    for (int o = 64; o > 0; o >>= 1) {
        if (tid < o)
            for (int b = 0; b < B; b++) red[b * 128 + tid] += red[b * 128 + tid + o];
        __syncthreads();
    }
    __shared__ float sv[MAXB], smu, srstd;
    if (tid < B) sv[tid] = red[tid * 128] + bf[f];
    __syncthreads();
    if (tid == 0) {
        float mu = 0.f;
        for (int b = 0; b < B; b++) mu += sv[b];
        mu /= (float)B;
        float var = 0.f;
        for (int b = 0; b < B; b++) { float dd = sv[b] - mu; var += dd * dd; }
        var /= (float)B;
        smu = mu; srstd = rsqrtf(var + EPS_BN);
    }
    __syncthreads();
    if (tid < B) g_resb[tid * FCC + f] = (sv[tid] - smu) * srstd * gf[f] + bef[f];
}

__global__ void __launch_bounds__(FCC) k_norm(float* __restrict__ out) {
    const int b = blockIdx.x, f = threadIdx.x;
    float v = g_resb[b * FCC + f];
    __shared__ float red[FCC];
    red[f] = v * v; __syncthreads();
    for (int o = FCC / 2; o > 0; o >>= 1) {
        if (f < o) red[f] += red[f + o];
        __syncthreads();
    }
    __shared__ float sinv;
    if (f == 0) sinv = 1.f / fmaxf(sqrtf(red[0]), 1e-12f);
    __syncthreads();
    out[(size_t)b * FCC + f] = v * sinv;
}

// ---------------------------------------------------------------------------
extern "C" void kernel_launch(void* const* d_in, const int* in_sizes, int n_in,
                              void* d_out, int out_size) {
    const float* x   = (const float*)d_in[0];
    const float* w1  = (const float*)d_in[1];
    const float* b1  = (const float*)d_in[2];
    const float* g1  = (const float*)d_in[3];
    const float* be1 = (const float*)d_in[4];
    const float* w2  = (const float*)d_in[5];
    const float* b2  = (const float*)d_in[6];
    const float* g2  = (const float*)d_in[7];
    const float* be2 = (const float*)d_in[8];
    const float* wf  = (const float*)d_in[9];
    const float* bf  = (const float*)d_in[10];
    const float* gf  = (const float*)d_in[11];
    const float* bef = (const float*)d_in[12];
    float* out = (float*)d_out;

    const int N = in_sizes[0] / C;
    const int B = out_size / (FCC + K2C + 1);
    const int L = N / B;
    const int rpc = L / SCH;
    const int nblk2 = N / 128;
    const int g2smem = G2_SMEM_FLOATS * 4;

    cudaFuncSetAttribute(k_gemm2, cudaFuncAttributeMaxDynamicSharedMemorySize, g2smem);

    k_gemm1<<<N / 256, 128>>>(x, w1, b1);
    k_fin1<<<K1C, 256>>>(g1, be1, N / 256, 1.f / (float)N);
    k_gemm2<<<nblk2, 256, g2smem>>>(w2, b2, N, nblk2);
    k_fin2<<<K2C, 256>>>(g2, be2, nblk2, 1.f / (float)N);
    k_pool<<<dim3(K2C / 128, B * SCH), 256>>>(x, N, L, rpc);
    k_poolred<<<(B * K2C * C + 255) / 256, 256>>>(1.f / (float)L, B);
    k_gpred<<<(B * K2C + 255) / 256, 256>>>(out, B, L);
    k_final<<<FCC, 128>>>(wf, bf, gf, bef, B);
    k_norm<<<B, FCC>>>(out);
}

// round 5
// speedup vs baseline: 2.4911x; 1.2523x over previous
#include <cuda_runtime.h>
#include <cstdint>

constexpr int C = 32, K1C = 128, K2C = 512, FCC = 256;
constexpr int MAXN = 524288, MAXB = 16, SCH = 16;
constexpr float EPS_BN = 1e-5f;

__device__ float g_h   [(size_t)MAXN * K1C];
__device__ float g_att [(size_t)K2C * MAXN];          // attT [512][N]
__device__ float g_p1s [(MAXN / 256) * K1C];
__device__ float g_p1q [(MAXN / 256) * K1C];
__device__ float g_p2s [(size_t)K2C * (MAXN / 128)];  // [ch][blk]
__device__ float g_p2q [(size_t)K2C * (MAXN / 128)];
__device__ float g_a1[K1C], g_bb1[K1C], g_a2[K2C], g_bb2[K2C];
__device__ float g_ppool[(size_t)MAXB * SCH * K2C * C];
__device__ float g_pgp  [(size_t)MAXB * SCH * K2C];
__device__ float g_pooled[(size_t)MAXB * K2C * C];
__device__ float g_resb [MAXB * FCC];

__device__ __forceinline__ float tf32r(float v) {
    float o; asm("cvt.rna.tf32.f32 %0, %1;" : "=f"(o) : "f"(v)); return o;
}
__device__ __forceinline__ void mma8(float* d, const uint32_t* a, const uint32_t* b) {
    asm volatile(
        "mma.sync.aligned.m16n8k8.row.col.f32.tf32.tf32.f32 "
        "{%0,%1,%2,%3}, {%4,%5,%6,%7}, {%8,%9}, {%0,%1,%2,%3};"
        : "+f"(d[0]), "+f"(d[1]), "+f"(d[2]), "+f"(d[3])
        : "r"(a[0]), "r"(a[1]), "r"(a[2]), "r"(a[3]), "r"(b[0]), "r"(b[1]));
}
__device__ __forceinline__ uint32_t s2u(const void* p) {
    uint32_t a;
    asm("{ .reg .u64 t; cvta.to.shared.u64 t, %1; cvt.u32.u64 %0, t; }" : "=r"(a) : "l"(p));
    return a;
}
__device__ __forceinline__ void cpasync16(uint32_t saddr, const void* g) {
    asm volatile("cp.async.cg.shared.global [%0], [%1], 16;" :: "r"(saddr), "l"(g));
}
#define CP_COMMIT() asm volatile("cp.async.commit_group;" ::: "memory")
#define CP_WAIT(n)  asm volatile("cp.async.wait_group %0;" :: "n"(n) : "memory")

// ---------------- GEMM1 (fp32 SIMT) ----------------
__global__ void __launch_bounds__(128) k_gemm1(const float* __restrict__ x,
                                               const float* __restrict__ w1,
                                               const float* __restrict__ b1) {
    __shared__ float sx[256 * C];
    const int k = threadIdx.x, p0 = blockIdx.x * 256;
    const float4* xg = reinterpret_cast<const float4*>(x) + (size_t)p0 * (C / 4);
    float4* sx4 = reinterpret_cast<float4*>(sx);
#pragma unroll
    for (int i = 0; i < 16; i++) sx4[threadIdx.x + i * 128] = xg[threadIdx.x + i * 128];
    float w[C];
#pragma unroll
    for (int c = 0; c < C; c++) w[c] = __ldg(&w1[k * C + c]);
    const float bias = __ldg(&b1[k]);
    __syncthreads();
    float s = 0.f, q = 0.f;
    float* hp = g_h + (size_t)p0 * K1C + k;
    for (int p = 0; p < 256; p++) {
        const float4* xr = reinterpret_cast<const float4*>(sx + p * C);
        float acc = bias;
#pragma unroll
        for (int c4 = 0; c4 < 8; c4++) {
            float4 v = xr[c4];
            acc = fmaf(w[c4 * 4 + 0], v.x, acc);
            acc = fmaf(w[c4 * 4 + 1], v.y, acc);
            acc = fmaf(w[c4 * 4 + 2], v.z, acc);
            acc = fmaf(w[c4 * 4 + 3], v.w, acc);
        }
        hp[(size_t)p * K1C] = acc;
        s += acc; q = fmaf(acc, acc, q);
    }
    g_p1s[blockIdx.x * K1C + k] = s;
    g_p1q[blockIdx.x * K1C + k] = q;
}

// ---------------- BN finalize ----------------
__global__ void k_fin1(const float* __restrict__ g, const float* __restrict__ be,
                       int nblk, float invN) {
    const int ch = blockIdx.x;
    __shared__ float rs[256], rq[256];
    float s = 0.f, q = 0.f;
    for (int i = threadIdx.x; i < nblk; i += 256) {
        s += g_p1s[i * K1C + ch]; q += g_p1q[i * K1C + ch];
    }
    rs[threadIdx.x] = s; rq[threadIdx.x] = q; __syncthreads();
    for (int o = 128; o > 0; o >>= 1) {
        if (threadIdx.x < o) { rs[threadIdx.x] += rs[threadIdx.x + o]; rq[threadIdx.x] += rq[threadIdx.x + o]; }
        __syncthreads();
    }
    if (threadIdx.x == 0) {
        float mu = rs[0] * invN, var = rq[0] * invN - mu * mu;
        float a = g[ch] * rsqrtf(var + EPS_BN);
        g_a1[ch] = a; g_bb1[ch] = be[ch] - mu * a;
    }
}
__global__ void k_fin2(const float* __restrict__ g, const float* __restrict__ be,
                       int nblk, float invN) {
    const int ch = blockIdx.x;
    __shared__ float rs[256], rq[256];
    float s = 0.f, q = 0.f;
    const float* ps = g_p2s + (size_t)ch * nblk;
    const float* pq = g_p2q + (size_t)ch * nblk;
    for (int i = threadIdx.x; i < nblk; i += 256) { s += ps[i]; q += pq[i]; }
    rs[threadIdx.x] = s; rq[threadIdx.x] = q; __syncthreads();
    for (int o = 128; o > 0; o >>= 1) {
        if (threadIdx.x < o) { rs[threadIdx.x] += rs[threadIdx.x + o]; rq[threadIdx.x] += rq[threadIdx.x + o]; }
        __syncthreads();
    }
    if (threadIdx.x == 0) {
        float mu = rs[0] * invN, var = rq[0] * invN - mu * mu;
        float a = g[ch] * rsqrtf(var + EPS_BN);
        g_a2[ch] = a; g_bb2[ch] = be[ch] - mu * a;
    }
}

// ---------------- GEMM2: tf32 mma.sync, 8 N-passes of 64, 2 CTAs/SM --------
// smem floats: As 16384 | Bs 8192 | sA1 128 | sB1 128 | sb2 512 | ps 256 | pq 256
constexpr int G2_OFF_BS = 16384, G2_OFF_SA1 = 24576, G2_OFF_SB1 = 24704;
constexpr int G2_OFF_SB2 = 24832, G2_OFF_PS = 25344, G2_OFF_PQ = 25600;
constexpr int G2_SMEM_FLOATS = 25856;

__global__ void __launch_bounds__(256, 2) k_gemm2(const float* __restrict__ w2,
                                                  const float* __restrict__ b2,
                                                  int Np, int nblk) {
    extern __shared__ float sm[];
    float* As = sm;
    float* Bs = sm + G2_OFF_BS;
    float* sA1 = sm + G2_OFF_SA1;
    float* sB1 = sm + G2_OFF_SB1;
    float* sb2 = sm + G2_OFF_SB2;
    float* ps  = sm + G2_OFF_PS;
    float* pq  = sm + G2_OFF_PQ;
    const int tid = threadIdx.x, lane = tid & 31, warp = tid >> 5;
    const int wm = warp >> 1, wn = warp & 1;
    const int gid = lane >> 2, tig = lane & 3;
    const int row0 = blockIdx.x * 128;

    if (tid < 128) { sA1[tid] = g_a1[tid]; sB1[tid] = g_bb1[tid]; }
    sb2[tid] = __ldg(&b2[tid]); sb2[tid + 256] = __ldg(&b2[tid + 256]);
    __syncthreads();

    // stage A (fragment order, xor-swizzled)
#pragma unroll
    for (int i = 0; i < 16; i++) {
        int q = tid + i * 256;
        int r = q >> 5, k4 = (q & 31) * 4;
        float4 v = *reinterpret_cast<const float4*>(&g_h[(size_t)(row0 + r) * K1C + k4]);
        float vv[4];
        vv[0] = tf32r(fmaxf(fmaf(sA1[k4 + 0], v.x, sB1[k4 + 0]), 0.f));
        vv[1] = tf32r(fmaxf(fmaf(sA1[k4 + 1], v.y, sB1[k4 + 1]), 0.f));
        vv[2] = tf32r(fmaxf(fmaf(sA1[k4 + 2], v.z, sB1[k4 + 2]), 0.f));
        vv[3] = tf32r(fmaxf(fmaf(sA1[k4 + 3], v.w, sB1[k4 + 3]), 0.f));
        int mt = r >> 4, rr = r & 15;
        int kt = k4 >> 3, reg = (rr >> 3) + ((k4 & 7) >> 2) * 2;
        int slotb = (rr & 7) * 4;
        float* base = As + (mt * 16 + kt) * 128;
#pragma unroll
        for (int j = 0; j < 4; j++)
            base[((slotb + j) ^ (kt & 7)) * 4 + reg] = vv[j];
    }

    for (int pass = 0; pass < 8; pass++) {
        // stage B = w2 rows [pass*64, +64)
#pragma unroll
        for (int i = 0; i < 8; i++) {
            int q = tid + i * 256;
            int r = q >> 5, k4 = (q & 31) * 4;
            float4 v = *reinterpret_cast<const float4*>(&w2[(size_t)(pass * 64 + r) * K1C + k4]);
            float vv[4] = { tf32r(v.x), tf32r(v.y), tf32r(v.z), tf32r(v.w) };
            int nt = r >> 3, rr = r & 7;
            int kt = k4 >> 3, reg = (k4 & 7) >> 2;
            int slotb = rr * 4;
            float* base = Bs + (nt * 16 + kt) * 64;
#pragma unroll
            for (int j = 0; j < 4; j++)
                base[((slotb + j) ^ (kt & 7)) * 2 + reg] = vv[j];
        }
        __syncthreads();

        float d[2][4][4] = {};
#pragma unroll
        for (int kt = 0; kt < 16; kt++) {
            int lp = lane ^ (kt & 7);
            uint32_t a[2][4], b[4][2];
#pragma unroll
            for (int mi = 0; mi < 2; mi++) {
                int mt = wm * 2 + mi;
                *reinterpret_cast<float4*>(a[mi]) =
                    *reinterpret_cast<const float4*>(&As[(mt * 16 + kt) * 128 + lp * 4]);
            }
#pragma unroll
            for (int ni = 0; ni < 4; ni++) {
                int nt = wn * 4 + ni;
                *reinterpret_cast<float2*>(b[ni]) =
                    *reinterpret_cast<const float2*>(&Bs[(nt * 16 + kt) * 64 + lp * 2]);
            }
#pragma unroll
            for (int mi = 0; mi < 2; mi++)
#pragma unroll
                for (int ni = 0; ni < 4; ni++)
                    mma8(d[mi][ni], a[mi], b[ni]);
        }

        // epilogue: bias, store attT, BN2 partials
#pragma unroll
        for (int ni = 0; ni < 4; ni++) {
#pragma unroll
            for (int par = 0; par < 2; par++) {
                int chp = wn * 32 + ni * 8 + tig * 2 + par;
                int ch = pass * 64 + chp;
                float bias = sb2[ch];
                float s = 0.f, qq = 0.f;
#pragma unroll
                for (int mi = 0; mi < 2; mi++) {
                    float v0 = d[mi][ni][par] + bias;
                    float v1 = d[mi][ni][par + 2] + bias;
                    int ptb = row0 + wm * 32 + mi * 16 + gid;
                    g_att[(size_t)ch * Np + ptb] = v0;
                    g_att[(size_t)ch * Np + ptb + 8] = v1;
                    s += v0 + v1;
                    qq = fmaf(v0, v0, qq); qq = fmaf(v1, v1, qq);
                }
#pragma unroll
                for (int o = 4; o < 32; o <<= 1) {
                    s  += __shfl_xor_sync(0xFFFFFFFFu, s, o);
                    qq += __shfl_xor_sync(0xFFFFFFFFu, qq, o);
                }
                if (gid == 0) { ps[wm * 64 + chp] = s; pq[wm * 64 + chp] = qq; }
            }
        }
        __syncthreads();
        if (tid < 64) {
            float s = ps[tid] + ps[64 + tid] + ps[128 + tid] + ps[192 + tid];
            float qq = pq[tid] + pq[64 + tid] + pq[128 + tid] + pq[192 + tid];
            g_p2s[(size_t)(pass * 64 + tid) * nblk + blockIdx.x] = s;
            g_p2q[(size_t)(pass * 64 + tid) * nblk + blockIdx.x] = qq;
        }
        __syncthreads();
    }
}

// ---------------- Pool: cp.async double-buffered, tf32 mma ----------------
// smem floats: attb[2][128][68]=17408 | xb[2][64][40]=5120 | sA2 128 | sB2 128
constexpr int P_AS = 68, P_XS = 40;
constexpr int P_OFF_XB = 2 * 128 * P_AS;              // 17408
constexpr int P_OFF_SA2 = P_OFF_XB + 2 * 64 * P_XS;   // 22528
constexpr int P_SMEM_FLOATS = P_OFF_SA2 + 256;        // 22784

__global__ void __launch_bounds__(256) k_pool(const float* __restrict__ x,
                                              int Np, int L, int rpc) {
    extern __shared__ float psm[];
    float* attb = psm;
    float* xb   = psm + P_OFF_XB;
    float* sA2  = psm + P_OFF_SA2;
    float* sB2c = sA2 + 128;
    const int tid = threadIdx.x, lane = tid & 31, warp = tid >> 5;
    const int gid = lane >> 2, tig = lane & 3;
    const int ch0 = blockIdx.x * 128;
    const int b = blockIdx.y / SCH, s = blockIdx.y % SCH;
    const int pt0g = b * L + s * rpc;
    const int nc = rpc / 64;
    const uint32_t attb_u = s2u(attb), xb_u = s2u(xb);

    if (tid < 128) { sA2[tid] = g_a2[ch0 + tid]; sB2c[tid] = g_bb2[ch0 + tid]; }
    // x pad cols 32..39 (col 32 = ones -> gp)
    for (int i = tid; i < 2 * 64 * 8; i += 256) {
        int buf = i / 512, r = (i / 8) % 64, c = i & 7;
        xb[buf * 64 * P_XS + r * P_XS + 32 + c] = (c == 0) ? 1.f : 0.f;
    }

    auto issue = [&](int ck, int buf) {
        const float* ga = &g_att[(size_t)ch0 * Np + pt0g + ck * 64];
        uint32_t sa = attb_u + buf * (128 * P_AS * 4);
#pragma unroll
        for (int i = 0; i < 8; i++) {
            int q = tid + i * 256;
            int r = q >> 4, c = q & 15;
            cpasync16(sa + (uint32_t)(r * P_AS + c * 4) * 4, ga + (size_t)r * Np + c * 4);
        }
        const float* gx = &x[(size_t)(pt0g + ck * 64) * C];
        uint32_t sx = xb_u + buf * (64 * P_XS * 4);
#pragma unroll
        for (int i = 0; i < 2; i++) {
            int q = tid + i * 256;
            int r = q >> 3, c = q & 7;
            cpasync16(sx + (uint32_t)(r * P_XS + c * 4) * 4, gx + r * C + c * 4);
        }
    };

    const float cA0 = g_a2[ch0 + warp * 16 + gid],     cB0 = g_bb2[ch0 + warp * 16 + gid];
    const float cA1 = g_a2[ch0 + warp * 16 + gid + 8], cB1 = g_bb2[ch0 + warp * 16 + gid + 8];

    float d[5][4] = {};
    issue(0, 0);
    CP_COMMIT();

    for (int ck = 0; ck < nc; ck++) {
        if (ck + 1 < nc) { issue(ck + 1, (ck + 1) & 1); CP_COMMIT(); CP_WAIT(1); }
        else             { CP_WAIT(0); }
        __syncthreads();

        const float* ab = attb + (ck & 1) * (128 * P_AS);
        const float* xv = xb + (ck & 1) * (64 * P_XS);
        const float* ar0 = ab + (warp * 16 + gid) * P_AS;
        const float* ar1 = ar0 + 8 * P_AS;
#pragma unroll
        for (int kt = 0; kt < 8; kt++) {
            uint32_t a[4];
            a[0] = __float_as_uint(tf32r(fmaxf(fmaf(cA0, ar0[kt * 8 + tig], cB0), 0.f)));
            a[1] = __float_as_uint(tf32r(fmaxf(fmaf(cA1, ar1[kt * 8 + tig], cB1), 0.f)));
            a[2] = __float_as_uint(tf32r(fmaxf(fmaf(cA0, ar0[kt * 8 + tig + 4], cB0), 0.f)));
            a[3] = __float_as_uint(tf32r(fmaxf(fmaf(cA1, ar1[kt * 8 + tig + 4], cB1), 0.f)));
#pragma unroll
            for (int ni = 0; ni < 5; ni++) {
                const float* br = xv + (kt * 8 + tig) * P_XS + ni * 8 + gid;
                uint32_t bb[2];
                bb[0] = __float_as_uint(tf32r(br[0]));
                bb[1] = __float_as_uint(tf32r(br[4 * P_XS]));
                mma8(d[ni], a, bb);
            }
        }
        __syncthreads();
    }

    const int seg = b * SCH + s;
#pragma unroll
    for (int ni = 0; ni < 5; ni++) {
#pragma unroll
        for (int c = 0; c < 4; c++) {
            int n = ni * 8 + tig * 2 + (c & 1);
            int ch = ch0 + warp * 16 + gid + 8 * (c >> 1);
            if (n < 32)
                g_ppool[((size_t)seg * K2C + ch) * C + n] = d[ni][c];
            else if (n == 32)
                g_pgp[(size_t)seg * K2C + ch] = d[ni][c];
        }
    }
}

__global__ void k_poolred(float invL, int B) {
    int idx = blockIdx.x * 256 + threadIdx.x;
    if (idx >= B * K2C * C) return;
    int b = idx / (K2C * C), rem = idx % (K2C * C);
    float s = 0.f;
#pragma unroll
    for (int t = 0; t < SCH; t++) s += g_ppool[(size_t)(b * SCH + t) * (K2C * C) + rem];
    g_pooled[idx] = s * invL;
}
__global__ void k_gpred(float* __restrict__ out, int B, int L) {
    int idx = blockIdx.x * 256 + threadIdx.x;
    if (idx >= B * K2C) return;
    int b = idx / K2C, k = idx % K2C;
    float s = 0.f;
#pragma unroll
    for (int t = 0; t < SCH; t++) s += g_pgp[(size_t)(b * SCH + t) * K2C + k];
    out[(size_t)B * FCC + (size_t)b * K2C + k] = s;
    if (k == 0) out[(size_t)B * (FCC + K2C) + b] = (float)L;
}

// ---------------- final FC + BN + L2 norm ----------------
__global__ void __launch_bounds__(128) k_final(const float* __restrict__ wf,
                                               const float* __restrict__ bf,
                                               const float* __restrict__ gf,
                                               const float* __restrict__ bef, int B) {
    const int f = blockIdx.x, tid = threadIdx.x, nq = (K2C * C) / 4;
    float acc[MAXB];
#pragma unroll
    for (int b = 0; b < MAXB; b++) acc[b] = 0.f;
    const float4* wf4 = reinterpret_cast<const float4*>(wf) + (size_t)f * nq;
    const float4* p4 = reinterpret_cast<const float4*>(g_pooled);
    for (int i = tid; i < nq; i += 128) {
        float4 wv = wf4[i];
        for (int b = 0; b < B; b++) {
            float4 pv = p4[(size_t)b * nq + i];
            acc[b] += wv.x * pv.x + wv.y * pv.y + wv.z * pv.z + wv.w * pv.w;
        }
    }
    __shared__ float red[MAXB * 128];
    for (int b = 0; b < B; b++) red[b * 128 + tid] = acc[b];
    __syncthreads();
    for (int o = 64; o > 0; o >>= 1) {
        if (tid < o)
            for (int b = 0; b < B; b++) red[b * 128 + tid] += red[b * 128 + tid + o];
        __syncthreads();
    }
    __shared__ float sv[MAXB], smu, srstd;
    if (tid < B) sv[tid] = red[tid * 128] + bf[f];
    __syncthreads();
    if (tid == 0) {
        float mu = 0.f;
        for (int b = 0; b < B; b++) mu += sv[b];
        mu /= (float)B;
        float var = 0.f;
        for (int b = 0; b < B; b++) { float dd = sv[b] - mu; var += dd * dd; }
        var /= (float)B;
        smu = mu; srstd = rsqrtf(var + EPS_BN);
    }
    __syncthreads();
    if (tid < B) g_resb[tid * FCC + f] = (sv[tid] - smu) * srstd * gf[f] + bef[f];
}

__global__ void __launch_bounds__(FCC) k_norm(float* __restrict__ out) {
    const int b = blockIdx.x, f = threadIdx.x;
    float v = g_resb[b * FCC + f];
    __shared__ float red[FCC];
    red[f] = v * v; __syncthreads();
    for (int o = FCC / 2; o > 0; o >>= 1) {
        if (f < o) red[f] += red[f + o];
        __syncthreads();
    }
    __shared__ float sinv;
    if (f == 0) sinv = 1.f / fmaxf(sqrtf(red[0]), 1e-12f);
    __syncthreads();
    out[(size_t)b * FCC + f] = v * sinv;
}

// ---------------------------------------------------------------------------
extern "C" void kernel_launch(void* const* d_in, const int* in_sizes, int n_in,
                              void* d_out, int out_size) {
    const float* x   = (const float*)d_in[0];
    const float* w1  = (const float*)d_in[1];
    const float* b1  = (const float*)d_in[2];
    const float* g1  = (const float*)d_in[3];
    const float* be1 = (const float*)d_in[4];
    const float* w2  = (const float*)d_in[5];
    const float* b2  = (const float*)d_in[6];
    const float* g2  = (const float*)d_in[7];
    const float* be2 = (const float*)d_in[8];
    const float* wf  = (const float*)d_in[9];
    const float* bf  = (const float*)d_in[10];
    const float* gf  = (const float*)d_in[11];
    const float* bef = (const float*)d_in[12];
    float* out = (float*)d_out;

    const int N = in_sizes[0] / C;
    const int B = out_size / (FCC + K2C + 1);
    const int L = N / B;
    const int rpc = L / SCH;
    const int nblk2 = N / 128;
    const int g2smem = G2_SMEM_FLOATS * 4;
    const int psmem = P_SMEM_FLOATS * 4;

    cudaFuncSetAttribute(k_gemm2, cudaFuncAttributeMaxDynamicSharedMemorySize, g2smem);
    cudaFuncSetAttribute(k_pool, cudaFuncAttributeMaxDynamicSharedMemorySize, psmem);

    k_gemm1<<<N / 256, 128>>>(x, w1, b1);
    k_fin1<<<K1C, 256>>>(g1, be1, N / 256, 1.f / (float)N);
    k_gemm2<<<nblk2, 256, g2smem>>>(w2, b2, N, nblk2);
    k_fin2<<<K2C, 256>>>(g2, be2, nblk2, 1.f / (float)N);
    k_pool<<<dim3(K2C / 128, B * SCH), 256, psmem>>>(x, N, L, rpc);
    k_poolred<<<(B * K2C * C + 255) / 256, 256>>>(1.f / (float)L, B);
    k_gpred<<<(B * K2C + 255) / 256, 256>>>(out, B, L);
    k_final<<<FCC, 128>>>(wf, bf, gf, bef, B);
    k_norm<<<B, FCC>>>(out);
}